// round 9
// baseline (speedup 1.0000x reference)
#include <cuda_runtime.h>
#include <cuda_fp16.h>
#include <cstdint>
#include <math.h>

// DeformAttn via ldmatrix + mma.sync (m16n8k16 fp16, fp32 accum) — base sm_103 ISA.
// Round 9: D_TILE=64 (1024 blocks), warp m16 x n64, persistent akK/akV (64 regs),
// SPLIT K-pass / V-pass so kp and vp are never co-live (fixes R6's register spills).
// W pre-swizzled fp16 scratch + cp.async staging; one barrier per sample.

namespace {
constexpr int Bn = 4, Cn = 128, Sn = 9, Dn = 16384;
constexpr int D_TILE = 64;
constexpr int NT = 256;
constexpr float ATT_SCALE = 0.25f;

constexpr int SM_WQ = 0;            // 3 x 32KB swizzled fp16 W
constexpr int SM_WK = 32768;
constexpr int SM_WV = 65536;
constexpr int SM_X0 = 98304;        // x tile [128c][64d] fp16, 16KB each
constexpr int SM_X1 = 114688;
constexpr int SM_TOTAL = 131072;
}

__device__ __align__(16) char g_wh[3 * 32768];

__device__ __forceinline__ uint32_t smem_u32(const void* p) {
    uint32_t a;
    asm("{ .reg .u64 t; cvta.to.shared.u64 t, %1; cvt.u32.u64 %0, t; }" : "=r"(a) : "l"(p));
    return a;
}
// W rows: 256B (128 halfwords), 16B chunks XOR-swizzled by row&7
__device__ __forceinline__ uint32_t swzW(int row, int colh) {
    int chunk = (colh >> 3) ^ (row & 7);
    return (uint32_t)(row * 256 + chunk * 16 + (colh & 7) * 2);
}
// x rows: 128B (64 halfwords), 16B chunks XOR-swizzled by row&7
__device__ __forceinline__ uint32_t swzX(int row, int colh) {
    int chunk = (colh >> 3) ^ (row & 7);
    return (uint32_t)(row * 128 + chunk * 16 + (colh & 7) * 2);
}
__device__ __forceinline__ void ldsm4(uint32_t r[4], uint32_t addr) {
    asm volatile("ldmatrix.sync.aligned.m8n8.x4.shared.b16 {%0,%1,%2,%3}, [%4];"
                 : "=r"(r[0]), "=r"(r[1]), "=r"(r[2]), "=r"(r[3]) : "r"(addr));
}
__device__ __forceinline__ void ldsm4t(uint32_t r[4], uint32_t addr) {
    asm volatile("ldmatrix.sync.aligned.m8n8.x4.trans.shared.b16 {%0,%1,%2,%3}, [%4];"
                 : "=r"(r[0]), "=r"(r[1]), "=r"(r[2]), "=r"(r[3]) : "r"(addr));
}
__device__ __forceinline__ void mma16816(float d[4], const uint32_t a[4], const uint32_t b[2]) {
    asm volatile(
        "mma.sync.aligned.m16n8k16.row.col.f32.f16.f16.f32 "
        "{%0,%1,%2,%3},{%4,%5,%6,%7},{%8,%9},{%0,%1,%2,%3};"
        : "+f"(d[0]), "+f"(d[1]), "+f"(d[2]), "+f"(d[3])
        : "r"(a[0]), "r"(a[1]), "r"(a[2]), "r"(a[3]), "r"(b[0]), "r"(b[1]));
}

// ---- prep kernel: W fp32 [o][c] -> swizzled fp16 scratch ----
__global__ void prep_w(const float* __restrict__ Wq, const float* __restrict__ Wk,
                       const float* __restrict__ Wv) {
    const int t = blockIdx.x * 256 + threadIdx.x;   // 0..12287
    const int w = t >> 12;
    const int rem = t & 4095;
    const int o = rem >> 5, f4 = rem & 31;
    const float* W = (w == 0) ? Wq : (w == 1) ? Wk : Wv;
    const float4 v = *reinterpret_cast<const float4*>(W + o * 128 + f4 * 4);
    char* dst = g_wh + w * 32768 + swzW(o, f4 * 4);
    *reinterpret_cast<__half2*>(dst)     = __floats2half2_rn(v.x, v.y);
    *reinterpret_cast<__half2*>(dst + 4) = __floats2half2_rn(v.z, v.w);
}

// ---- x staging: one wave = 64 c-rows, 4 float4/thread (256 threads) ----
__device__ __forceinline__ void pf_load(float4 pf[4], const float* __restrict__ src,
                                        long cstride, int wave, int tid) {
#pragma unroll
    for (int i = 0; i < 4; i++) {
        const int g = i * 256 + tid;
        const int c = wave * 64 + (g >> 4), d4 = (g & 15) * 4;
        pf[i] = *reinterpret_cast<const float4*>(src + (long)c * cstride + d4);
    }
}
__device__ __forceinline__ void pf_store(char* xb, const float4 pf[4], int wave, int tid) {
#pragma unroll
    for (int i = 0; i < 4; i++) {
        const int g = i * 256 + tid;
        const int c = wave * 64 + (g >> 4), d4 = (g & 15) * 4;
        const uint32_t off = swzX(c, d4);
        *reinterpret_cast<__half2*>(xb + off)     = __floats2half2_rn(pf[i].x, pf[i].y);
        *reinterpret_cast<__half2*>(xb + off + 4) = __floats2half2_rn(pf[i].z, pf[i].w);
    }
}

__global__ void __launch_bounds__(NT, 1)
deform_attn_hmma(const float* __restrict__ q,  const float* __restrict__ kv,
                 const float* __restrict__ bq, const float* __restrict__ bv,
                 float* __restrict__ out)
{
    extern __shared__ char smem[];
    const uint32_t sb = smem_u32(smem);
    const int tid = threadIdx.x, lane = tid & 31, wid = tid >> 5;
    const int b = blockIdx.y;
    const int dt = blockIdx.x * D_TILE;

    // A-fragment address (warp's 16 rows = one head)
    const int a_row  = wid * 16 + (lane & 7) + ((lane >> 3) & 1) * 8;
    const int a_colq = (lane >> 4) * 8;
    // B-fragment ldsm4t indices
    const int tl = lane >> 3;
    const int b_crem = (tl & 1) * 8 + (lane & 7);
    const int b_drem = (tl >> 1) * 8;

    // ---- stage all three W via identity cp.async ----
#pragma unroll
    for (int i = 0; i < 24; i++) {
        const uint32_t dst = sb + (uint32_t)(tid * 16 + i * 4096);
        const char* src = g_wh + tid * 16 + i * 4096;
        asm volatile("cp.async.cg.shared.global [%0], [%1], 16;" :: "r"(dst), "l"(src));
    }
    asm volatile("cp.async.commit_group;" ::: "memory");

    // ---- stage q tile ----
    {
        float4 pf[4];
        pf_load(pf, q + (long)b * Cn * Dn + dt, (long)Dn, 0, tid);
        pf_store(smem + SM_X0, pf, 0, tid);
        pf_load(pf, q + (long)b * Cn * Dn + dt, (long)Dn, 1, tid);
        pf_store(smem + SM_X0, pf, 1, tid);
    }
    asm volatile("cp.async.wait_group 0;" ::: "memory");
    __syncthreads();

    // ---- persistent A fragments for Wk, Wv ----
    uint32_t akK[8][4], akV[8][4];
#pragma unroll
    for (int ks = 0; ks < 8; ks++) {
        const int colh = ks * 16 + a_colq;
        ldsm4(akK[ks], sb + SM_WK + swzW(a_row, colh));
        ldsm4(akV[ks], sb + SM_WV + swzW(a_row, colh));
    }

    // ---- Q projection: m16 x n64 ----
    float qp[8][4];
#pragma unroll
    for (int n = 0; n < 8; n++) qp[n][0] = qp[n][1] = qp[n][2] = qp[n][3] = 0.0f;
#pragma unroll
    for (int ks = 0; ks < 8; ks++) {
        uint32_t aq[4];
        ldsm4(aq, sb + SM_WQ + swzW(a_row, ks * 16 + a_colq));
        const int c = ks * 16 + b_crem;
#pragma unroll
        for (int nn = 0; nn < 4; nn++) {
            uint32_t r4[4];
            ldsm4t(r4, sb + SM_X0 + swzX(c, nn * 16 + b_drem));
            uint32_t f0[2] = {r4[0], r4[1]}, f1[2] = {r4[2], r4[3]};
            mma16816(qp[nn * 2],     aq, f0);
            mma16816(qp[nn * 2 + 1], aq, f1);
        }
    }

    const int r0 = wid * 16 + (lane >> 2);
    {
        const float b0 = bq[r0], b1 = bq[r0 + 8];
#pragma unroll
        for (int n = 0; n < 8; n++) {
            qp[n][0] += b0; qp[n][1] += b0; qp[n][2] += b1; qp[n][3] += b1;
        }
    }

    float acc[8][4], den[8][2];
#pragma unroll
    for (int n = 0; n < 8; n++) {
        acc[n][0] = acc[n][1] = acc[n][2] = acc[n][3] = 0.0f;
        den[n][0] = den[n][1] = 0.0f;
    }

    __syncthreads();   // Q-proj readers done with X0
    {
        float4 pf[4];
        pf_load(pf, kv + (long)(b * Cn) * Sn * Dn + dt, (long)Sn * Dn, 0, tid);
        pf_store(smem + SM_X0, pf, 0, tid);
        pf_load(pf, kv + (long)(b * Cn) * Sn * Dn + dt, (long)Sn * Dn, 1, tid);
        pf_store(smem + SM_X0, pf, 1, tid);
    }
    __syncthreads();

    for (int s = 0; s < Sn; s++) {
        const uint32_t xb = sb + ((s & 1) ? SM_X1 : SM_X0);
        char* nxt = smem + (((s + 1) & 1) ? SM_X1 : SM_X0);
        const float* nsrc = kv + ((long)(b * Cn) * Sn + (s + 1)) * Dn + dt;

        float4 pf[4];
        if (s + 1 < Sn) pf_load(pf, nsrc, (long)Sn * Dn, 0, tid);

        // ---- K-pass (B-frags from smem, A persistent) ----
        float kp[8][4];
#pragma unroll
        for (int n = 0; n < 8; n++) kp[n][0] = kp[n][1] = kp[n][2] = kp[n][3] = 0.0f;
#pragma unroll
        for (int ks = 0; ks < 8; ks++) {
            const int c = ks * 16 + b_crem;
#pragma unroll
            for (int nn = 0; nn < 4; nn++) {
                uint32_t r4[4];
                ldsm4t(r4, xb + swzX(c, nn * 16 + b_drem));
                uint32_t f0[2] = {r4[0], r4[1]}, f1[2] = {r4[2], r4[3]};
                mma16816(kp[nn * 2],     akK[ks], f0);
                mma16816(kp[nn * 2 + 1], akK[ks], f1);
            }
        }

        // ---- softmax weights (kp dies here) ----
        float w[8][2];
#pragma unroll
        for (int n = 0; n < 8; n++) {
            float pe = qp[n][0] * kp[n][0] + qp[n][2] * kp[n][2];
            float po = qp[n][1] * kp[n][1] + qp[n][3] * kp[n][3];
            pe += __shfl_xor_sync(0xffffffffu, pe, 4);
            pe += __shfl_xor_sync(0xffffffffu, pe, 8);
            pe += __shfl_xor_sync(0xffffffffu, pe, 16);
            po += __shfl_xor_sync(0xffffffffu, po, 4);
            po += __shfl_xor_sync(0xffffffffu, po, 8);
            po += __shfl_xor_sync(0xffffffffu, po, 16);
            const float we = __expf(ATT_SCALE * pe);
            const float wo = __expf(ATT_SCALE * po);
            w[n][0] = we; w[n][1] = wo;
            den[n][0] += we; den[n][1] += wo;
        }

        if (s + 1 < Sn) {
            pf_store(nxt, pf, 0, tid);
            pf_load(pf, nsrc, (long)Sn * Dn, 1, tid);
        }

        // ---- V-pass (vp replaces kp's registers) ----
        float vp[8][4];
#pragma unroll
        for (int n = 0; n < 8; n++) vp[n][0] = vp[n][1] = vp[n][2] = vp[n][3] = 0.0f;
#pragma unroll
        for (int ks = 0; ks < 8; ks++) {
            const int c = ks * 16 + b_crem;
#pragma unroll
            for (int nn = 0; nn < 4; nn++) {
                uint32_t r4[4];
                ldsm4t(r4, xb + swzX(c, nn * 16 + b_drem));
                uint32_t f0[2] = {r4[0], r4[1]}, f1[2] = {r4[2], r4[3]};
                mma16816(vp[nn * 2],     akV[ks], f0);
                mma16816(vp[nn * 2 + 1], akV[ks], f1);
            }
        }
#pragma unroll
        for (int n = 0; n < 8; n++) {
            acc[n][0] = fmaf(w[n][0], vp[n][0], acc[n][0]);
            acc[n][1] = fmaf(w[n][1], vp[n][1], acc[n][1]);
            acc[n][2] = fmaf(w[n][0], vp[n][2], acc[n][2]);
            acc[n][3] = fmaf(w[n][1], vp[n][3], acc[n][3]);
        }

        if (s + 1 < Sn) pf_store(nxt, pf, 1, tid);
        __syncthreads();
    }

    // ---- output: out = acc/den + bv ----
    {
        const float bv0 = bv[r0], bv1 = bv[r0 + 8];
#pragma unroll
        for (int n = 0; n < 8; n++) {
            float* dst = out + ((long)(b * Cn + r0)) * Dn + dt + n * 8 + (lane & 3) * 2;
            const float de = den[n][0], dz = den[n][1];
            float2 v0 = make_float2(acc[n][0] / de + bv0, acc[n][1] / dz + bv0);
            float2 v1 = make_float2(acc[n][2] / de + bv1, acc[n][3] / dz + bv1);
            *reinterpret_cast<float2*>(dst) = v0;
            *reinterpret_cast<float2*>(dst + (long)8 * Dn) = v1;
        }
    }
}

extern "C" void kernel_launch(void* const* d_in, const int* in_sizes, int n_in,
                              void* d_out, int out_size) {
    const float* q  = (const float*)d_in[0];
    const float* kv = (const float*)d_in[1];
    const float* Wq = (const float*)d_in[2];
    const float* bq = (const float*)d_in[3];
    const float* Wk = (const float*)d_in[4];
    // d_in[5] = bk: unused (softmax-invariant)
    const float* Wv = (const float*)d_in[6];
    const float* bv = (const float*)d_in[7];
    float* out = (float*)d_out;

    prep_w<<<48, 256>>>(Wq, Wk, Wv);

    cudaFuncSetAttribute(deform_attn_hmma,
                         cudaFuncAttributeMaxDynamicSharedMemorySize, SM_TOTAL);
    dim3 grid(Dn / D_TILE, Bn);   // 256 x 4 = 1024 blocks
    deform_attn_hmma<<<grid, NT, SM_TOTAL>>>(q, kv, bq, bv, out);
}